// round 16
// baseline (speedup 1.0000x reference)
#include <cuda_runtime.h>
#include <cuda_fp16.h>
#include <cstdint>

#define T_SEQ   2048
#define HEADS   16
#define GROUPS  4
#define D_HEAD  128
#define TK_     (T_SEQ + 1)
#define QKV_DIM 3072
#define C_DIM   2048
#define HD      (HEADS * D_HEAD)
#define SCALE_Q 0.08838834764831845f   // 1/sqrt(128)

// ---------------- scratch (device globals; no allocation allowed) ----------
__device__ float g_qkv[T_SEQ * QKV_DIM];

__device__ __align__(16) __half g_xh [C_DIM  * C_DIM];
__device__ __align__(16) __half g_wah[QKV_DIM * C_DIM];
__device__ __align__(16) __half g_oh [T_SEQ * HD];
__device__ __align__(16) __half g_wph[C_DIM * HD];

__device__ __align__(16) __half g_qh [T_SEQ * HD];
__device__ __align__(16) __half g_kh [GROUPS * TK_ * D_HEAD];
__device__ __align__(16) __half g_vh [GROUPS * TK_ * D_HEAD];

// ---------------- low-level helpers -----------------------------------------
__device__ __forceinline__ uint32_t smem_u32(const void* p) {
    uint32_t a;
    asm("{ .reg .u64 t; cvta.to.shared.u64 t, %1; cvt.u32.u64 %0, t; }" : "=r"(a) : "l"(p));
    return a;
}
#define CP_ASYNC16(sm, gp) \
    asm volatile("cp.async.cg.shared.global [%0], [%1], 16;" :: "r"(sm), "l"(gp) : "memory")
#define CP_ASYNC16Z(sm, gp, sz) \
    asm volatile("cp.async.cg.shared.global [%0], [%1], 16, %2;" :: "r"(sm), "l"(gp), "r"(sz) : "memory")
#define CP_COMMIT() asm volatile("cp.async.commit_group;" ::: "memory")
#define CP_WAIT(n)  asm volatile("cp.async.wait_group %0;" :: "n"(n) : "memory")

#define LDMATRIX_X4(r, a) \
    asm volatile("ldmatrix.sync.aligned.m8n8.x4.shared.b16 {%0,%1,%2,%3}, [%4];" \
        : "=r"((r)[0]), "=r"((r)[1]), "=r"((r)[2]), "=r"((r)[3]) : "r"(a))
#define LDMATRIX_X2(r, a) \
    asm volatile("ldmatrix.sync.aligned.m8n8.x2.shared.b16 {%0,%1}, [%2];" \
        : "=r"((r)[0]), "=r"((r)[1]) : "r"(a))
#define LDMATRIX_X2T(r, a) \
    asm volatile("ldmatrix.sync.aligned.m8n8.x2.trans.shared.b16 {%0,%1}, [%2];" \
        : "=r"((r)[0]), "=r"((r)[1]) : "r"(a))

#define MMA_F16(d, a, b) \
    asm volatile("mma.sync.aligned.m16n8k16.row.col.f32.f16.f16.f32 " \
        "{%0,%1,%2,%3},{%4,%5,%6,%7},{%8,%9},{%0,%1,%2,%3};" \
        : "+f"((d)[0]), "+f"((d)[1]), "+f"((d)[2]), "+f"((d)[3]) \
        : "r"((a)[0]), "r"((a)[1]), "r"((a)[2]), "r"((a)[3]), "r"((b)[0]), "r"((b)[1]))

__device__ __forceinline__ uint32_t pack_h2(__half lo, __half hi) {
    __half2 t = __halves2half2(lo, hi);
    return *reinterpret_cast<uint32_t*>(&t);
}

// ---------------- HMMA fp16 GEMM: 8 warps, 32x64 warp tile (R15) ------------
#define BM 128
#define BN 128
#define BK 64
#define PITCH_B 144
#define TILE_BYTES (BM * PITCH_B)             // 18432
#define STAGE_BYTES (2 * TILE_BYTES)          // 36864
#define GEMM_SMEM (3 * STAGE_BYTES)           // 110592

__global__ void __launch_bounds__(256, 2)
k_gemm_mma(const __half* __restrict__ Ah, const __half* __restrict__ Bh,
           float* __restrict__ C, int Ndim, int Kdim)
{
    extern __shared__ char sm[];
    const uint32_t sbase = smem_u32(sm);
    const int tid  = threadIdx.x;
    const int lane = tid & 31;
    const int wid  = tid >> 5;
    const int wm   = wid >> 1;
    const int wn   = wid & 1;
    const int rowBase = blockIdx.y * BM;
    const int colBase = blockIdx.x * BN;

    auto load_stage = [&](int s, int k0) {
        const uint32_t b = sbase + s * STAGE_BYTES;
        #pragma unroll
        for (int i = 0; i < 4; ++i) {
            const int cid = tid + i * 256;
            const int r = cid >> 3, c = cid & 7;
            CP_ASYNC16(b + (uint32_t)(r * PITCH_B + c * 16),
                       Ah + (size_t)(rowBase + r) * Kdim + k0 + c * 8);
        }
        #pragma unroll
        for (int i = 0; i < 4; ++i) {
            const int cid = tid + i * 256;
            const int r = cid >> 3, c = cid & 7;
            CP_ASYNC16(b + TILE_BYTES + (uint32_t)(r * PITCH_B + c * 16),
                       Bh + (size_t)(colBase + r) * Kdim + k0 + c * 8);
        }
        CP_COMMIT();
    };

    float acc[2][8][4];
    #pragma unroll
    for (int i = 0; i < 2; ++i)
        #pragma unroll
        for (int j = 0; j < 8; ++j)
            #pragma unroll
            for (int r = 0; r < 4; ++r) acc[i][j][r] = 0.f;

    const int niter = Kdim / BK;
    load_stage(0, 0);
    load_stage(1, BK);

    const int aRow  = (lane & 15);
    const int aK    = ((lane >> 4) << 3);
    const int b4Row = (lane & 7) + ((lane >> 4) << 3);
    const int b4K   = (((lane >> 3) & 1) << 3);

    for (int it = 0; it < niter; ++it) {
        if (it + 1 < niter) { CP_WAIT(1); } else { CP_WAIT(0); }
        __syncthreads();
        if (it + 2 < niter) load_stage((it + 2) % 3, (it + 2) * BK);

        const int s = it % 3;
        const uint32_t tA0 = sbase + s * STAGE_BYTES;
        const uint32_t tB0 = tA0 + TILE_BYTES;

        #pragma unroll
        for (int kk = 0; kk < BK; kk += 16) {
            uint32_t ah[2][4], bh[8][2];
            #pragma unroll
            for (int mf = 0; mf < 2; ++mf) {
                uint32_t addr = tA0 + (uint32_t)((wm*32 + mf*16 + aRow) * PITCH_B + (kk + aK) * 2);
                LDMATRIX_X4(ah[mf], addr);
            }
            #pragma unroll
            for (int np = 0; np < 4; ++np) {
                uint32_t q[4];
                uint32_t addr = tB0 + (uint32_t)((wn*64 + np*16 + b4Row) * PITCH_B + (kk + b4K) * 2);
                LDMATRIX_X4(q, addr);
                bh[2*np    ][0] = q[0]; bh[2*np    ][1] = q[1];
                bh[2*np + 1][0] = q[2]; bh[2*np + 1][1] = q[3];
            }
            #pragma unroll
            for (int mf = 0; mf < 2; ++mf)
                #pragma unroll
                for (int nf = 0; nf < 8; ++nf) MMA_F16(acc[mf][nf], ah[mf], bh[nf]);
        }
    }

    const int gq  = lane >> 2;
    const int tig = lane & 3;
    #pragma unroll
    for (int mf = 0; mf < 2; ++mf) {
        const int row = rowBase + wm*32 + mf*16 + gq;
        #pragma unroll
        for (int nf = 0; nf < 8; ++nf) {
            const int col = colBase + wn*64 + nf*8 + 2*tig;
            *(float2*)(C + (size_t)row * Ndim + col)       = make_float2(acc[mf][nf][0], acc[mf][nf][1]);
            *(float2*)(C + (size_t)(row + 8) * Ndim + col) = make_float2(acc[mf][nf][2], acc[mf][nf][3]);
        }
    }
}

// ---------------- fp32 -> fp16 convert ---------------------------------------
__global__ void __launch_bounds__(256)
k_cvt(const float* __restrict__ src, __half* __restrict__ hi)
{
    int i = (blockIdx.x * 256 + threadIdx.x) * 4;
    float4 v = *(const float4*)(src + i);
    union { __half b[4]; uint2 u; } H;
    H.b[0] = __float2half_rn(v.x); H.b[1] = __float2half_rn(v.y);
    H.b[2] = __float2half_rn(v.z); H.b[3] = __float2half_rn(v.w);
    *(uint2*)(hi + i) = H.u;
}

// ---------------- fused RoPE/scatter/sink (single launch) --------------------
// blocks [0,8192): rope_q; [8192,10240): rope_k; [10240,14336): copy_v; 14336: sink
#define PREP_BLOCKS 14337
__global__ void __launch_bounds__(256)
k_prep(const float* __restrict__ cosb, const float* __restrict__ sinb,
       const float* __restrict__ k_sink, const float* __restrict__ v_sink)
{
    const int b = blockIdx.x;
    const int tid = threadIdx.x;
    if (b < 8192) {                                 // rope_q: T*H*64 items
        int idx = b * 256 + tid;
        int j = idx & 63;
        int h = (idx >> 6) & 15;
        int t = idx >> 10;
        const float* base = g_qkv + t*QKV_DIM + (h >> 2)*768 + (h & 3)*128;
        float x1 = base[j], x2 = base[64 + j];
        float c = cosb[t*64 + j], s = sinb[t*64 + j];
        size_t o = (size_t)t * HD + h * D_HEAD;
        g_qh[o + j]      = __float2half_rn((x1*c - x2*s) * SCALE_Q);
        g_qh[o + 64 + j] = __float2half_rn((x1*s + x2*c) * SCALE_Q);
    } else if (b < 10240) {                         // rope_k: T*G*64 items
        int idx = (b - 8192) * 256 + tid;
        int j = idx & 63;
        int g = (idx >> 6) & 3;
        int t = idx >> 8;
        const float* base = g_qkv + t*QKV_DIM + g*768 + 512;
        float x1 = base[j], x2 = base[64 + j];
        float c = cosb[t*64 + j], s = sinb[t*64 + j];
        size_t o = (size_t)(g*TK_ + t + 1) * D_HEAD;
        g_kh[o + j]      = __float2half_rn(x1*c - x2*s);
        g_kh[o + 64 + j] = __float2half_rn(x1*s + x2*c);
    } else if (b < 14336) {                         // copy_v: T*G*128 items
        int idx = (b - 10240) * 256 + tid;
        int d = idx & 127;
        int g = (idx >> 7) & 3;
        int t = idx >> 9;
        g_vh[(size_t)(g*TK_ + t + 1) * D_HEAD + d] =
            __float2half_rn(g_qkv[t*QKV_DIM + g*768 + 640 + d]);
    } else {                                        // sink: 512 items
        int idx = tid;
        if (idx < GROUPS * D_HEAD) {
            int g = idx >> 7;
            int d = idx & 127;
            size_t o = (size_t)(g*TK_) * D_HEAD + d;
            g_kh[o] = __float2half_rn(k_sink[idx]);
            g_vh[o] = __float2half_rn(v_sink[idx]);
        }
        if (idx + 256 < GROUPS * D_HEAD) {
            int i2 = idx + 256;
            int g = i2 >> 7;
            int d = i2 & 127;
            size_t o = (size_t)(g*TK_) * D_HEAD + d;
            g_kh[o] = __float2half_rn(k_sink[i2]);
            g_vh[o] = __float2half_rn(v_sink[i2]);
        }
    }
}

// ---------------- flash attention (R12/R15, unchanged) -----------------------
#define AT_CN    64
#define AT_PITCH 272
#define AT_TILE  (AT_CN * AT_PITCH)           // 17408
#define AT_STAGE (2 * AT_TILE)                // 34816
#define ATT_SMEM (3 * AT_STAGE)               // 104448

__global__ void __launch_bounds__(256, 1)
k_attn_mma()
{
    extern __shared__ char sm[];
    const uint32_t sbase = smem_u32(sm);
    const int tid  = threadIdx.x;
    const int lane = tid & 31;
    const int wq   = tid >> 5;
    const int gq   = lane >> 2;
    const int tig  = lane & 3;

    const int h  = blockIdx.y;
    const int g  = h >> 2;
    const int i0 = (gridDim.x - 1 - blockIdx.x) * 128;

    const __half* Kgh = g_kh + (size_t)g * TK_ * D_HEAD;
    const __half* Vgh = g_vh + (size_t)g * TK_ * D_HEAD;

    const int iA = i0 + wq*16 + gq;
    const int iB = iA + 8;
    uint32_t Qh[8][4];
    {
        const size_t r0 = (size_t)iA * HD + h * D_HEAD;
        const size_t r1 = (size_t)iB * HD + h * D_HEAD;
        #pragma unroll
        for (int kf = 0; kf < 8; ++kf) {
            const int col = kf*16 + tig*2;
            Qh[kf][0] = *(const uint32_t*)(g_qh + r0 + col);
            Qh[kf][1] = *(const uint32_t*)(g_qh + r1 + col);
            Qh[kf][2] = *(const uint32_t*)(g_qh + r0 + col + 8);
            Qh[kf][3] = *(const uint32_t*)(g_qh + r1 + col + 8);
        }
    }

    float O[16][4];
    #pragma unroll
    for (int i = 0; i < 16; ++i)
        #pragma unroll
        for (int r = 0; r < 4; ++r) O[i][r] = 0.f;
    float mA = __int_as_float(0xff800000);
    float mB = __int_as_float(0xff800000);
    float lA = 0.f, lB = 0.f;

    const int jlo = max(0, i0 - 1022);
    const int jhi = i0 + 128;
    const int nchunk = (jhi - jlo + AT_CN) / AT_CN;

    const int loA = iA - 1022, hiA = iA + 1;
    const int loB = iB - 1022, hiB = iB + 1;

    auto load_chunk = [&](int s, int j0) {
        #pragma unroll
        for (int t = 0; t < 8; ++t) {
            const int tensor = t >> 2;
            const int inner  = tid + (t & 3) * 256;
            const int row = inner >> 4, c16 = inner & 15;
            int j = j0 + row;
            uint32_t sz = (j <= 2048) ? 16u : 0u;
            if (j > 2048) j = 2048;
            uint32_t dst = sbase + s*AT_STAGE + tensor*AT_TILE
                         + (uint32_t)(row*AT_PITCH + c16*16);
            const __half* base = (tensor == 0) ? Kgh : Vgh;
            CP_ASYNC16Z(dst, base + (size_t)j * D_HEAD + c16*8, sz);
        }
        CP_COMMIT();
    };

    load_chunk(0, jlo);
    if (nchunk > 1) load_chunk(1, jlo + AT_CN);

    for (int c = 0; c < nchunk; ++c) {
        const int j0 = jlo + c * AT_CN;
        if (c + 1 < nchunk) { CP_WAIT(1); } else { CP_WAIT(0); }
        __syncthreads();
        if (c + 2 < nchunk) load_chunk((c + 2) % 3, j0 + 2*AT_CN);

        const int s = c % 3;
        const uint32_t bKh = sbase + s*AT_STAGE;
        const uint32_t bVh = bKh + AT_TILE;

        float S[8][4];
        const int kRow = lane & 7;
        const int kOff = ((lane >> 3) & 1) * 16;
        #pragma unroll
        for (int nf = 0; nf < 8; ++nf) {
            #pragma unroll
            for (int r = 0; r < 4; ++r) S[nf][r] = 0.f;
            #pragma unroll
            for (int kf = 0; kf < 8; ++kf) {
                uint32_t b[2];
                LDMATRIX_X2(b, bKh + (uint32_t)((nf*8 + kRow) * AT_PITCH + kf*32 + kOff));
                MMA_F16(S[nf], Qh[kf], b);
            }
        }

        float mcA = __int_as_float(0xff800000), mcB = __int_as_float(0xff800000);
        #pragma unroll
        for (int nf = 0; nf < 8; ++nf) {
            const int j = j0 + nf*8 + tig*2;
            #pragma unroll
            for (int e = 0; e < 2; ++e) {
                const int jj = j + e;
                if (jj < loA || jj > hiA) S[nf][e] = __int_as_float(0xff800000);
                mcA = fmaxf(mcA, S[nf][e]);
                if (jj < loB || jj > hiB) S[nf][2+e] = __int_as_float(0xff800000);
                mcB = fmaxf(mcB, S[nf][2+e]);
            }
        }
        mcA = fmaxf(mcA, __shfl_xor_sync(0xffffffffu, mcA, 1));
        mcA = fmaxf(mcA, __shfl_xor_sync(0xffffffffu, mcA, 2));
        mcB = fmaxf(mcB, __shfl_xor_sync(0xffffffffu, mcB, 1));
        mcB = fmaxf(mcB, __shfl_xor_sync(0xffffffffu, mcB, 2));

        const float mAn = fmaxf(mA, mcA);
        const float mBn = fmaxf(mB, mcB);
        const float baseA = fmaxf(mAn, -1e30f);
        const float baseB = fmaxf(mBn, -1e30f);
        const float corrA = __expf(mA - baseA);
        const float corrB = __expf(mB - baseB);
        mA = mAn; mB = mBn;
        lA *= corrA; lB *= corrB;
        #pragma unroll
        for (int i = 0; i < 16; ++i) {
            O[i][0] *= corrA; O[i][1] *= corrA;
            O[i][2] *= corrB; O[i][3] *= corrB;
        }

        uint32_t Ph[4][4];
        #pragma unroll
        for (int nf = 0; nf < 8; ++nf) {
            float p0 = __expf(S[nf][0] - baseA);
            float p1 = __expf(S[nf][1] - baseA);
            float p2 = __expf(S[nf][2] - baseB);
            float p3 = __expf(S[nf][3] - baseB);
            lA += p0 + p1; lB += p2 + p3;
            const int kf2 = nf >> 1, half = (nf & 1) * 2;
            Ph[kf2][half + 0] = pack_h2(__float2half_rn(p0), __float2half_rn(p1));
            Ph[kf2][half + 1] = pack_h2(__float2half_rn(p2), __float2half_rn(p3));
        }

        const int vRow = (lane & 7) + ((lane >> 3) & 1) * 8;
        #pragma unroll
        for (int nf2 = 0; nf2 < 16; ++nf2) {
            #pragma unroll
            for (int kf2 = 0; kf2 < 4; ++kf2) {
                uint32_t b[2];
                LDMATRIX_X2T(b, bVh + (uint32_t)((kf2*16 + vRow) * AT_PITCH + nf2*16));
                MMA_F16(O[nf2], Ph[kf2], b);
            }
        }
    }

    lA += __shfl_xor_sync(0xffffffffu, lA, 1);
    lA += __shfl_xor_sync(0xffffffffu, lA, 2);
    lB += __shfl_xor_sync(0xffffffffu, lB, 1);
    lB += __shfl_xor_sync(0xffffffffu, lB, 2);
    const float invA = 1.f / lA;
    const float invB = 1.f / lB;

    const size_t rA = (size_t)iA * HD + h * D_HEAD;
    const size_t rB = (size_t)iB * HD + h * D_HEAD;
    #pragma unroll
    for (int nf2 = 0; nf2 < 16; ++nf2) {
        const int col = nf2*8 + tig*2;
        *(uint32_t*)(g_oh + rA + col) = pack_h2(__float2half_rn(O[nf2][0] * invA),
                                                __float2half_rn(O[nf2][1] * invA));
        *(uint32_t*)(g_oh + rB + col) = pack_h2(__float2half_rn(O[nf2][2] * invB),
                                                __float2half_rn(O[nf2][3] * invB));
    }
}

// ---------------- launch -----------------------------------------------------
extern "C" void kernel_launch(void* const* d_in, const int* in_sizes, int n_in,
                              void* d_out, int out_size)
{
    const float* x      = (const float*)d_in[0];
    const float* cosb   = (const float*)d_in[1];
    const float* sinb   = (const float*)d_in[2];
    const float* W_attn = (const float*)d_in[3];
    const float* W_proj = (const float*)d_in[4];
    const float* ksink  = (const float*)d_in[5];
    const float* vsink  = (const float*)d_in[6];
    float* out = (float*)d_out;

    static bool init = false;
    static cudaStream_t sA, sB;
    static cudaEvent_t evFork, evA, evB;
    if (!init) {
        cudaStreamCreate(&sA);
        cudaStreamCreate(&sB);
        cudaEventCreateWithFlags(&evFork, cudaEventDisableTiming);
        cudaEventCreateWithFlags(&evA, cudaEventDisableTiming);
        cudaEventCreateWithFlags(&evB, cudaEventDisableTiming);
        cudaFuncSetAttribute(k_gemm_mma, cudaFuncAttributeMaxDynamicSharedMemorySize, GEMM_SMEM);
        cudaFuncSetAttribute(k_attn_mma, cudaFuncAttributeMaxDynamicSharedMemorySize, ATT_SMEM);
        init = true;
    }

    __half *xh, *wah, *oh, *wph;
    float *qkv;
    cudaGetSymbolAddress((void**)&xh,  g_xh);
    cudaGetSymbolAddress((void**)&wah, g_wah);
    cudaGetSymbolAddress((void**)&oh,  g_oh);
    cudaGetSymbolAddress((void**)&wph, g_wph);
    cudaGetSymbolAddress((void**)&qkv, g_qkv);

    // fork: three conversions in parallel on separate streams
    cudaEventRecord(evFork, 0);
    cudaStreamWaitEvent(sA, evFork, 0);
    cudaStreamWaitEvent(sB, evFork, 0);

    k_cvt<<<(C_DIM*C_DIM)/1024, 256>>>(x, xh);                     // stream 0
    k_cvt<<<(QKV_DIM*C_DIM)/1024, 256, 0, sA>>>(W_attn, wah);      // stream A
    k_cvt<<<(C_DIM*HD)/1024, 256, 0, sB>>>(W_proj, wph);           // stream B
    cudaEventRecord(evA, sA);
    cudaEventRecord(evB, sB);

    // GEMM1 needs x + W_attn
    cudaStreamWaitEvent(0, evA, 0);
    k_gemm_mma<<<dim3(QKV_DIM/BN, T_SEQ/BM), 256, GEMM_SMEM>>>(
        xh, wah, qkv, QKV_DIM, C_DIM);

    // fused RoPE/scatter/sink
    k_prep<<<PREP_BLOCKS, 256>>>(cosb, sinb, ksink, vsink);

    // flash attention
    k_attn_mma<<<dim3(T_SEQ/128, HEADS), 256, ATT_SMEM>>>();

    // GEMM2 needs W_proj
    cudaStreamWaitEvent(0, evB, 0);
    k_gemm_mma<<<dim3(C_DIM/BN, T_SEQ/BM), 256, GEMM_SMEM>>>(
        oh, wph, out, C_DIM, HD);
}

// round 17
// speedup vs baseline: 1.4845x; 1.4845x over previous
#include <cuda_runtime.h>
#include <cuda_fp16.h>
#include <cstdint>

#define T_SEQ   2048
#define HEADS   16
#define GROUPS  4
#define D_HEAD  128
#define TK_     (T_SEQ + 1)
#define QKV_DIM 3072
#define C_DIM   2048
#define HD      (HEADS * D_HEAD)
#define SCALE_Q 0.08838834764831845f   // 1/sqrt(128)

// ---------------- scratch (device globals; no allocation allowed) ----------
__device__ float g_qkv[T_SEQ * QKV_DIM];

__device__ __align__(16) __half g_xh [C_DIM  * C_DIM];
__device__ __align__(16) __half g_wah[QKV_DIM * C_DIM];
__device__ __align__(16) __half g_oh [T_SEQ * HD];
__device__ __align__(16) __half g_wph[C_DIM * HD];

__device__ __align__(16) __half g_qh [T_SEQ * HD];
__device__ __align__(16) __half g_kh [GROUPS * TK_ * D_HEAD];
__device__ __align__(16) __half g_vh [GROUPS * TK_ * D_HEAD];

// ---------------- low-level helpers -----------------------------------------
__device__ __forceinline__ uint32_t smem_u32(const void* p) {
    uint32_t a;
    asm("{ .reg .u64 t; cvta.to.shared.u64 t, %1; cvt.u32.u64 %0, t; }" : "=r"(a) : "l"(p));
    return a;
}
#define CP_ASYNC16(sm, gp) \
    asm volatile("cp.async.cg.shared.global [%0], [%1], 16;" :: "r"(sm), "l"(gp) : "memory")
#define CP_ASYNC16Z(sm, gp, sz) \
    asm volatile("cp.async.cg.shared.global [%0], [%1], 16, %2;" :: "r"(sm), "l"(gp), "r"(sz) : "memory")
#define CP_COMMIT() asm volatile("cp.async.commit_group;" ::: "memory")
#define CP_WAIT(n)  asm volatile("cp.async.wait_group %0;" :: "n"(n) : "memory")

#define LDMATRIX_X4(r, a) \
    asm volatile("ldmatrix.sync.aligned.m8n8.x4.shared.b16 {%0,%1,%2,%3}, [%4];" \
        : "=r"((r)[0]), "=r"((r)[1]), "=r"((r)[2]), "=r"((r)[3]) : "r"(a))
#define LDMATRIX_X2(r, a) \
    asm volatile("ldmatrix.sync.aligned.m8n8.x2.shared.b16 {%0,%1}, [%2];" \
        : "=r"((r)[0]), "=r"((r)[1]) : "r"(a))
#define LDMATRIX_X2T(r, a) \
    asm volatile("ldmatrix.sync.aligned.m8n8.x2.trans.shared.b16 {%0,%1}, [%2];" \
        : "=r"((r)[0]), "=r"((r)[1]) : "r"(a))

#define MMA_F16(d, a, b) \
    asm volatile("mma.sync.aligned.m16n8k16.row.col.f32.f16.f16.f32 " \
        "{%0,%1,%2,%3},{%4,%5,%6,%7},{%8,%9},{%0,%1,%2,%3};" \
        : "+f"((d)[0]), "+f"((d)[1]), "+f"((d)[2]), "+f"((d)[3]) \
        : "r"((a)[0]), "r"((a)[1]), "r"((a)[2]), "r"((a)[3]), "r"((b)[0]), "r"((b)[1]))

__device__ __forceinline__ uint32_t pack_h2(__half lo, __half hi) {
    __half2 t = __halves2half2(lo, hi);
    return *reinterpret_cast<uint32_t*>(&t);
}

// ---------------- HMMA fp16 GEMM: 8 warps, 32x64 warp tile (R15) ------------
#define BM 128
#define BN 128
#define BK 64
#define PITCH_B 144
#define TILE_BYTES (BM * PITCH_B)             // 18432
#define STAGE_BYTES (2 * TILE_BYTES)          // 36864
#define GEMM_SMEM (3 * STAGE_BYTES)           // 110592

__global__ void __launch_bounds__(256, 2)
k_gemm_mma(const __half* __restrict__ Ah, const __half* __restrict__ Bh,
           float* __restrict__ C, int Ndim, int Kdim)
{
    extern __shared__ char sm[];
    const uint32_t sbase = smem_u32(sm);
    const int tid  = threadIdx.x;
    const int lane = tid & 31;
    const int wid  = tid >> 5;
    const int wm   = wid >> 1;
    const int wn   = wid & 1;
    const int rowBase = blockIdx.y * BM;
    const int colBase = blockIdx.x * BN;

    auto load_stage = [&](int s, int k0) {
        const uint32_t b = sbase + s * STAGE_BYTES;
        #pragma unroll
        for (int i = 0; i < 4; ++i) {
            const int cid = tid + i * 256;
            const int r = cid >> 3, c = cid & 7;
            CP_ASYNC16(b + (uint32_t)(r * PITCH_B + c * 16),
                       Ah + (size_t)(rowBase + r) * Kdim + k0 + c * 8);
        }
        #pragma unroll
        for (int i = 0; i < 4; ++i) {
            const int cid = tid + i * 256;
            const int r = cid >> 3, c = cid & 7;
            CP_ASYNC16(b + TILE_BYTES + (uint32_t)(r * PITCH_B + c * 16),
                       Bh + (size_t)(colBase + r) * Kdim + k0 + c * 8);
        }
        CP_COMMIT();
    };

    float acc[2][8][4];
    #pragma unroll
    for (int i = 0; i < 2; ++i)
        #pragma unroll
        for (int j = 0; j < 8; ++j)
            #pragma unroll
            for (int r = 0; r < 4; ++r) acc[i][j][r] = 0.f;

    const int niter = Kdim / BK;
    load_stage(0, 0);
    load_stage(1, BK);

    const int aRow  = (lane & 15);
    const int aK    = ((lane >> 4) << 3);
    const int b4Row = (lane & 7) + ((lane >> 4) << 3);
    const int b4K   = (((lane >> 3) & 1) << 3);

    for (int it = 0; it < niter; ++it) {
        if (it + 1 < niter) { CP_WAIT(1); } else { CP_WAIT(0); }
        __syncthreads();
        if (it + 2 < niter) load_stage((it + 2) % 3, (it + 2) * BK);

        const int s = it % 3;
        const uint32_t tA0 = sbase + s * STAGE_BYTES;
        const uint32_t tB0 = tA0 + TILE_BYTES;

        #pragma unroll
        for (int kk = 0; kk < BK; kk += 16) {
            uint32_t ah[2][4], bh[8][2];
            #pragma unroll
            for (int mf = 0; mf < 2; ++mf) {
                uint32_t addr = tA0 + (uint32_t)((wm*32 + mf*16 + aRow) * PITCH_B + (kk + aK) * 2);
                LDMATRIX_X4(ah[mf], addr);
            }
            #pragma unroll
            for (int np = 0; np < 4; ++np) {
                uint32_t q[4];
                uint32_t addr = tB0 + (uint32_t)((wn*64 + np*16 + b4Row) * PITCH_B + (kk + b4K) * 2);
                LDMATRIX_X4(q, addr);
                bh[2*np    ][0] = q[0]; bh[2*np    ][1] = q[1];
                bh[2*np + 1][0] = q[2]; bh[2*np + 1][1] = q[3];
            }
            #pragma unroll
            for (int mf = 0; mf < 2; ++mf)
                #pragma unroll
                for (int nf = 0; nf < 8; ++nf) MMA_F16(acc[mf][nf], ah[mf], bh[nf]);
        }
    }

    const int gq  = lane >> 2;
    const int tig = lane & 3;
    #pragma unroll
    for (int mf = 0; mf < 2; ++mf) {
        const int row = rowBase + wm*32 + mf*16 + gq;
        #pragma unroll
        for (int nf = 0; nf < 8; ++nf) {
            const int col = colBase + wn*64 + nf*8 + 2*tig;
            *(float2*)(C + (size_t)row * Ndim + col)       = make_float2(acc[mf][nf][0], acc[mf][nf][1]);
            *(float2*)(C + (size_t)(row + 8) * Ndim + col) = make_float2(acc[mf][nf][2], acc[mf][nf][3]);
        }
    }
}

// ---------------- fp32 -> fp16 convert ---------------------------------------
__global__ void __launch_bounds__(256)
k_cvt(const float* __restrict__ src, __half* __restrict__ hi)
{
    int i = (blockIdx.x * 256 + threadIdx.x) * 4;
    float4 v = *(const float4*)(src + i);
    union { __half b[4]; uint2 u; } H;
    H.b[0] = __float2half_rn(v.x); H.b[1] = __float2half_rn(v.y);
    H.b[2] = __float2half_rn(v.z); H.b[3] = __float2half_rn(v.w);
    *(uint2*)(hi + i) = H.u;
}

// ---------------- fused RoPE/scatter/sink (single launch) --------------------
#define PREP_BLOCKS 14337
__global__ void __launch_bounds__(256)
k_prep(const float* __restrict__ cosb, const float* __restrict__ sinb,
       const float* __restrict__ k_sink, const float* __restrict__ v_sink)
{
    const int b = blockIdx.x;
    const int tid = threadIdx.x;
    if (b < 8192) {                                 // rope_q
        int idx = b * 256 + tid;
        int j = idx & 63;
        int h = (idx >> 6) & 15;
        int t = idx >> 10;
        const float* base = g_qkv + t*QKV_DIM + (h >> 2)*768 + (h & 3)*128;
        float x1 = base[j], x2 = base[64 + j];
        float c = cosb[t*64 + j], s = sinb[t*64 + j];
        size_t o = (size_t)t * HD + h * D_HEAD;
        g_qh[o + j]      = __float2half_rn((x1*c - x2*s) * SCALE_Q);
        g_qh[o + 64 + j] = __float2half_rn((x1*s + x2*c) * SCALE_Q);
    } else if (b < 10240) {                         // rope_k
        int idx = (b - 8192) * 256 + tid;
        int j = idx & 63;
        int g = (idx >> 6) & 3;
        int t = idx >> 8;
        const float* base = g_qkv + t*QKV_DIM + g*768 + 512;
        float x1 = base[j], x2 = base[64 + j];
        float c = cosb[t*64 + j], s = sinb[t*64 + j];
        size_t o = (size_t)(g*TK_ + t + 1) * D_HEAD;
        g_kh[o + j]      = __float2half_rn(x1*c - x2*s);
        g_kh[o + 64 + j] = __float2half_rn(x1*s + x2*c);
    } else if (b < 14336) {                         // copy_v
        int idx = (b - 10240) * 256 + tid;
        int d = idx & 127;
        int g = (idx >> 7) & 3;
        int t = idx >> 9;
        g_vh[(size_t)(g*TK_ + t + 1) * D_HEAD + d] =
            __float2half_rn(g_qkv[t*QKV_DIM + g*768 + 640 + d]);
    } else {                                        // sink
        int idx = tid;
        if (idx < GROUPS * D_HEAD) {
            int g = idx >> 7;
            int d = idx & 127;
            size_t o = (size_t)(g*TK_) * D_HEAD + d;
            g_kh[o] = __float2half_rn(k_sink[idx]);
            g_vh[o] = __float2half_rn(v_sink[idx]);
        }
        if (idx + 256 < GROUPS * D_HEAD) {
            int i2 = idx + 256;
            int g = i2 >> 7;
            int d = i2 & 127;
            size_t o = (size_t)(g*TK_) * D_HEAD + d;
            g_kh[o] = __float2half_rn(k_sink[i2]);
            g_vh[o] = __float2half_rn(v_sink[i2]);
        }
    }
}

// ---------------- flash attention (R12/R15, unchanged) -----------------------
#define AT_CN    64
#define AT_PITCH 272
#define AT_TILE  (AT_CN * AT_PITCH)           // 17408
#define AT_STAGE (2 * AT_TILE)                // 34816
#define ATT_SMEM (3 * AT_STAGE)               // 104448

__global__ void __launch_bounds__(256, 1)
k_attn_mma()
{
    extern __shared__ char sm[];
    const uint32_t sbase = smem_u32(sm);
    const int tid  = threadIdx.x;
    const int lane = tid & 31;
    const int wq   = tid >> 5;
    const int gq   = lane >> 2;
    const int tig  = lane & 3;

    const int h  = blockIdx.y;
    const int g  = h >> 2;
    const int i0 = (gridDim.x - 1 - blockIdx.x) * 128;

    const __half* Kgh = g_kh + (size_t)g * TK_ * D_HEAD;
    const __half* Vgh = g_vh + (size_t)g * TK_ * D_HEAD;

    const int iA = i0 + wq*16 + gq;
    const int iB = iA + 8;
    uint32_t Qh[8][4];
    {
        const size_t r0 = (size_t)iA * HD + h * D_HEAD;
        const size_t r1 = (size_t)iB * HD + h * D_HEAD;
        #pragma unroll
        for (int kf = 0; kf < 8; ++kf) {
            const int col = kf*16 + tig*2;
            Qh[kf][0] = *(const uint32_t*)(g_qh + r0 + col);
            Qh[kf][1] = *(const uint32_t*)(g_qh + r1 + col);
            Qh[kf][2] = *(const uint32_t*)(g_qh + r0 + col + 8);
            Qh[kf][3] = *(const uint32_t*)(g_qh + r1 + col + 8);
        }
    }

    float O[16][4];
    #pragma unroll
    for (int i = 0; i < 16; ++i)
        #pragma unroll
        for (int r = 0; r < 4; ++r) O[i][r] = 0.f;
    float mA = __int_as_float(0xff800000);
    float mB = __int_as_float(0xff800000);
    float lA = 0.f, lB = 0.f;

    const int jlo = max(0, i0 - 1022);
    const int jhi = i0 + 128;
    const int nchunk = (jhi - jlo + AT_CN) / AT_CN;

    const int loA = iA - 1022, hiA = iA + 1;
    const int loB = iB - 1022, hiB = iB + 1;

    auto load_chunk = [&](int s, int j0) {
        #pragma unroll
        for (int t = 0; t < 8; ++t) {
            const int tensor = t >> 2;
            const int inner  = tid + (t & 3) * 256;
            const int row = inner >> 4, c16 = inner & 15;
            int j = j0 + row;
            uint32_t sz = (j <= 2048) ? 16u : 0u;
            if (j > 2048) j = 2048;
            uint32_t dst = sbase + s*AT_STAGE + tensor*AT_TILE
                         + (uint32_t)(row*AT_PITCH + c16*16);
            const __half* base = (tensor == 0) ? Kgh : Vgh;
            CP_ASYNC16Z(dst, base + (size_t)j * D_HEAD + c16*8, sz);
        }
        CP_COMMIT();
    };

    load_chunk(0, jlo);
    if (nchunk > 1) load_chunk(1, jlo + AT_CN);

    for (int c = 0; c < nchunk; ++c) {
        const int j0 = jlo + c * AT_CN;
        if (c + 1 < nchunk) { CP_WAIT(1); } else { CP_WAIT(0); }
        __syncthreads();
        if (c + 2 < nchunk) load_chunk((c + 2) % 3, j0 + 2*AT_CN);

        const int s = c % 3;
        const uint32_t bKh = sbase + s*AT_STAGE;
        const uint32_t bVh = bKh + AT_TILE;

        float S[8][4];
        const int kRow = lane & 7;
        const int kOff = ((lane >> 3) & 1) * 16;
        #pragma unroll
        for (int nf = 0; nf < 8; ++nf) {
            #pragma unroll
            for (int r = 0; r < 4; ++r) S[nf][r] = 0.f;
            #pragma unroll
            for (int kf = 0; kf < 8; ++kf) {
                uint32_t b[2];
                LDMATRIX_X2(b, bKh + (uint32_t)((nf*8 + kRow) * AT_PITCH + kf*32 + kOff));
                MMA_F16(S[nf], Qh[kf], b);
            }
        }

        float mcA = __int_as_float(0xff800000), mcB = __int_as_float(0xff800000);
        #pragma unroll
        for (int nf = 0; nf < 8; ++nf) {
            const int j = j0 + nf*8 + tig*2;
            #pragma unroll
            for (int e = 0; e < 2; ++e) {
                const int jj = j + e;
                if (jj < loA || jj > hiA) S[nf][e] = __int_as_float(0xff800000);
                mcA = fmaxf(mcA, S[nf][e]);
                if (jj < loB || jj > hiB) S[nf][2+e] = __int_as_float(0xff800000);
                mcB = fmaxf(mcB, S[nf][2+e]);
            }
        }
        mcA = fmaxf(mcA, __shfl_xor_sync(0xffffffffu, mcA, 1));
        mcA = fmaxf(mcA, __shfl_xor_sync(0xffffffffu, mcA, 2));
        mcB = fmaxf(mcB, __shfl_xor_sync(0xffffffffu, mcB, 1));
        mcB = fmaxf(mcB, __shfl_xor_sync(0xffffffffu, mcB, 2));

        const float mAn = fmaxf(mA, mcA);
        const float mBn = fmaxf(mB, mcB);
        const float baseA = fmaxf(mAn, -1e30f);
        const float baseB = fmaxf(mBn, -1e30f);
        const float corrA = __expf(mA - baseA);
        const float corrB = __expf(mB - baseB);
        mA = mAn; mB = mBn;
        lA *= corrA; lB *= corrB;
        #pragma unroll
        for (int i = 0; i < 16; ++i) {
            O[i][0] *= corrA; O[i][1] *= corrA;
            O[i][2] *= corrB; O[i][3] *= corrB;
        }

        uint32_t Ph[4][4];
        #pragma unroll
        for (int nf = 0; nf < 8; ++nf) {
            float p0 = __expf(S[nf][0] - baseA);
            float p1 = __expf(S[nf][1] - baseA);
            float p2 = __expf(S[nf][2] - baseB);
            float p3 = __expf(S[nf][3] - baseB);
            lA += p0 + p1; lB += p2 + p3;
            const int kf2 = nf >> 1, half = (nf & 1) * 2;
            Ph[kf2][half + 0] = pack_h2(__float2half_rn(p0), __float2half_rn(p1));
            Ph[kf2][half + 1] = pack_h2(__float2half_rn(p2), __float2half_rn(p3));
        }

        const int vRow = (lane & 7) + ((lane >> 3) & 1) * 8;
        #pragma unroll
        for (int nf2 = 0; nf2 < 16; ++nf2) {
            #pragma unroll
            for (int kf2 = 0; kf2 < 4; ++kf2) {
                uint32_t b[2];
                LDMATRIX_X2T(b, bVh + (uint32_t)((kf2*16 + vRow) * AT_PITCH + nf2*16));
                MMA_F16(O[nf2], Ph[kf2], b);
            }
        }
    }

    lA += __shfl_xor_sync(0xffffffffu, lA, 1);
    lA += __shfl_xor_sync(0xffffffffu, lA, 2);
    lB += __shfl_xor_sync(0xffffffffu, lB, 1);
    lB += __shfl_xor_sync(0xffffffffu, lB, 2);
    const float invA = 1.f / lA;
    const float invB = 1.f / lB;

    const size_t rA = (size_t)iA * HD + h * D_HEAD;
    const size_t rB = (size_t)iB * HD + h * D_HEAD;
    #pragma unroll
    for (int nf2 = 0; nf2 < 16; ++nf2) {
        const int col = nf2*8 + tig*2;
        *(uint32_t*)(g_oh + rA + col) = pack_h2(__float2half_rn(O[nf2][0] * invA),
                                                __float2half_rn(O[nf2][1] * invA));
        *(uint32_t*)(g_oh + rB + col) = pack_h2(__float2half_rn(O[nf2][2] * invB),
                                                __float2half_rn(O[nf2][3] * invB));
    }
}

// ---------------- launch -----------------------------------------------------
extern "C" void kernel_launch(void* const* d_in, const int* in_sizes, int n_in,
                              void* d_out, int out_size)
{
    const float* x      = (const float*)d_in[0];
    const float* cosb   = (const float*)d_in[1];
    const float* sinb   = (const float*)d_in[2];
    const float* W_attn = (const float*)d_in[3];
    const float* W_proj = (const float*)d_in[4];
    const float* ksink  = (const float*)d_in[5];
    const float* vsink  = (const float*)d_in[6];
    float* out = (float*)d_out;

    cudaFuncSetAttribute(k_gemm_mma, cudaFuncAttributeMaxDynamicSharedMemorySize, GEMM_SMEM);
    cudaFuncSetAttribute(k_attn_mma, cudaFuncAttributeMaxDynamicSharedMemorySize, ATT_SMEM);

    __half *xh, *wah, *oh, *wph;
    float *qkv;
    cudaGetSymbolAddress((void**)&xh,  g_xh);
    cudaGetSymbolAddress((void**)&wah, g_wah);
    cudaGetSymbolAddress((void**)&oh,  g_oh);
    cudaGetSymbolAddress((void**)&wph, g_wph);
    cudaGetSymbolAddress((void**)&qkv, g_qkv);

    // 1) convert inputs to fp16 (single stream, in order)
    k_cvt<<<(C_DIM*C_DIM)/1024, 256>>>(x, xh);
    k_cvt<<<(QKV_DIM*C_DIM)/1024, 256>>>(W_attn, wah);
    k_cvt<<<(C_DIM*HD)/1024, 256>>>(W_proj, wph);

    // 2) qkv = x @ W_attn^T
    k_gemm_mma<<<dim3(QKV_DIM/BN, T_SEQ/BM), 256, GEMM_SMEM>>>(
        xh, wah, qkv, QKV_DIM, C_DIM);

    // 3) fused RoPE/scatter/sink
    k_prep<<<PREP_BLOCKS, 256>>>(cosb, sinb, ksink, vsink);

    // 4) flash attention
    k_attn_mma<<<dim3(T_SEQ/128, HEADS), 256, ATT_SMEM>>>();

    // 5) y = O @ W_proj^T
    k_gemm_mma<<<dim3(C_DIM/BN, T_SEQ/BM), 256, GEMM_SMEM>>>(
        oh, wph, out, C_DIM, HD);
}